// round 1
// baseline (speedup 1.0000x reference)
#include <cuda_runtime.h>
#include <math.h>

// Problem dims
#define NB 2
#define NC 16
#define NAM 4
#define NHEADS 8
#define NF 1024
#define NW 1024
#define NHD 128

// ---------------- scratch (device globals; no runtime allocation) ----------------
__device__ float g_y[3][8][NF * NW];     // conv outputs for q,k,v   [tensor][b*4+am][h*1024+w]
__device__ float g_t[3][8][NW * NF];     // qT,kT,vT                 [tensor][b*4+am][w*1024+f]
__device__ float g_a[8][NW * NF];        // attention out            [b*4+am][w*1024+f]
__device__ float g_ao[8][NW * NF];       // after dw channel mix     [b*4+am][w*1024+h]
__device__ float g_a2[8][NF * NW];       // after wo_pw              [b*4+am][f*1024+w]
__device__ float g_rmax[NB * NAM * NHEADS * NW];
__device__ float g_rinv[NB * NAM * NHEADS * NW];
__device__ float g_cos[NW * (NHD / 2)];
__device__ float g_sin[NW * (NHD / 2)];

// ---------------- helpers ----------------
__device__ __forceinline__ int rowoff(int i, int ty) {
    return (i < 4) ? (ty * 4 + i) : (64 + ty * 4 + (i - 4));
}

template <int ASTR, int BSTR>
__device__ __forceinline__ void gemm_step(const float* As, const float* Bs,
                                          int tx, int ty, float (&acc)[8][8]) {
#pragma unroll
    for (int kk = 0; kk < 8; kk++) {
        float4 a0 = *(const float4*)(As + kk * ASTR + ty * 4);
        float4 a1 = *(const float4*)(As + kk * ASTR + 64 + ty * 4);
        float4 b0 = *(const float4*)(Bs + kk * BSTR + tx * 4);
        float4 b1 = *(const float4*)(Bs + kk * BSTR + 64 + tx * 4);
        float av[8] = {a0.x, a0.y, a0.z, a0.w, a1.x, a1.y, a1.z, a1.w};
        float bv[8] = {b0.x, b0.y, b0.z, b0.w, b1.x, b1.y, b1.z, b1.w};
#pragma unroll
        for (int i = 0; i < 8; i++)
#pragma unroll
            for (int j = 0; j < 8; j++)
                acc[i][j] += av[i] * bv[j];
    }
}

// ---------------- RoPE table init (fp64 for accuracy; 64K threads, trivial) ----------------
__global__ void rope_init_kernel() {
    int idx = blockIdx.x * blockDim.x + threadIdx.x;
    if (idx >= NW * 64) return;
    int w = idx >> 6, j = idx & 63;
    double inv = exp(-((double)(2 * j) / (double)NHD) * log(10000.0));
    double ang = (double)w * inv;
    g_cos[idx] = (float)cos(ang);
    g_sin[idx] = (float)sin(ang);
}

// ---------------- conv 3x3 (16 -> 4) producing q,k,v conv outputs in one pass ----------------
__global__ __launch_bounds__(256) void conv_qkv_kernel(
    const float* __restrict__ x,
    const float* __restrict__ wq, const float* __restrict__ bq,
    const float* __restrict__ wk, const float* __restrict__ bk,
    const float* __restrict__ wv, const float* __restrict__ bv) {
    __shared__ float sx[4][18][68];
    __shared__ float sw[3 * 4 * 16 * 9];  // [t][am][ch][tap]
    const int b = blockIdx.x;
    const int h0 = blockIdx.y * 16;
    const int w0 = blockIdx.z * 64;
    const int tx = threadIdx.x, ty = threadIdx.y;
    const int tid = ty * 16 + tx;

    for (int i = tid; i < 576; i += 256) {
        sw[i] = wq[i];
        sw[576 + i] = wk[i];
        sw[1152 + i] = wv[i];
    }

    float acc[12][4];
#pragma unroll
    for (int o = 0; o < 12; o++)
#pragma unroll
        for (int p = 0; p < 4; p++) acc[o][p] = 0.f;

    for (int cc = 0; cc < 16; cc += 4) {
        __syncthreads();
        for (int e = tid; e < 4 * 18 * 66; e += 256) {
            int ch = e / (18 * 66);
            int r = (e / 66) % 18;
            int cl = e % 66;
            int gh = h0 + r - 1, gw = w0 + cl - 1;
            float v = 0.f;
            if ((unsigned)gh < 1024u && (unsigned)gw < 1024u)
                v = x[(((size_t)(b * 16 + cc + ch)) << 20) + gh * 1024 + gw];
            sx[ch][r][cl] = v;
        }
        __syncthreads();
#pragma unroll
        for (int ch = 0; ch < 4; ch++) {
#pragma unroll
            for (int dy = 0; dy < 3; dy++) {
                float xr[6];
#pragma unroll
                for (int i = 0; i < 6; i++) xr[i] = sx[ch][ty + dy][tx * 4 + i];
#pragma unroll
                for (int dx = 0; dx < 3; dx++) {
                    int widx = (cc + ch) * 9 + dy * 3 + dx;
#pragma unroll
                    for (int o = 0; o < 12; o++) {
                        float wv_ = sw[(o >> 2) * 576 + (o & 3) * 144 + widx];
#pragma unroll
                        for (int p = 0; p < 4; p++) acc[o][p] += wv_ * xr[p + dx];
                    }
                }
            }
        }
    }

    int gh = h0 + ty, gw = w0 + tx * 4;
#pragma unroll
    for (int t = 0; t < 3; t++) {
        const float* bias = (t == 0) ? bq : (t == 1) ? bk : bv;
#pragma unroll
        for (int m = 0; m < 4; m++) {
            float bb = bias[m];
            float4 v = make_float4(acc[t * 4 + m][0] + bb, acc[t * 4 + m][1] + bb,
                                   acc[t * 4 + m][2] + bb, acc[t * 4 + m][3] + bb);
            *(float4*)&g_y[t][b * 4 + m][gh * 1024 + gw] = v;
        }
    }
}

// ---------------- per-map pw linear: OutT[w,f] = sum_h Wt[f,h] * Y[h,w]; optional RoPE ----------------
__global__ __launch_bounds__(256) void gemm_pw_kernel(const float* __restrict__ Wpw,
                                                      int t, int do_rope) {
    const int m0 = blockIdx.x * 128;  // w
    const int n0 = blockIdx.y * 128;  // f
    const int b4 = blockIdx.z;
    const int am = b4 & 3;
    const float* Y = g_y[t][b4];
    const float* Wt = Wpw + ((size_t)am << 20);
    float* Out = g_t[t][b4];

    __shared__ float As[8 * 128];
    __shared__ float Bs[8 * 132];
    const int tid = threadIdx.x;
    const int tx = tid & 15, ty = tid >> 4;
    const int ka = tid >> 5, ma = (tid & 31) * 4;  // A direct
    const int nb = tid >> 1, kb = (tid & 1) * 4;   // B transpose

    float acc[8][8];
#pragma unroll
    for (int i = 0; i < 8; i++)
#pragma unroll
        for (int j = 0; j < 8; j++) acc[i][j] = 0.f;

    float4 pa = *(const float4*)&Y[(size_t)ka * 1024 + m0 + ma];
    float4 pb = *(const float4*)&Wt[(size_t)(n0 + nb) * 1024 + kb];

    for (int k0 = 0; k0 < 1024; k0 += 8) {
        *(float4*)&As[ka * 128 + ma] = pa;
        Bs[(kb + 0) * 132 + nb] = pb.x;
        Bs[(kb + 1) * 132 + nb] = pb.y;
        Bs[(kb + 2) * 132 + nb] = pb.z;
        Bs[(kb + 3) * 132 + nb] = pb.w;
        __syncthreads();
        if (k0 + 8 < 1024) {
            pa = *(const float4*)&Y[(size_t)(k0 + 8 + ka) * 1024 + m0 + ma];
            pb = *(const float4*)&Wt[(size_t)(n0 + nb) * 1024 + k0 + 8 + kb];
        }
        gemm_step<128, 132>(As, Bs, tx, ty, acc);
        __syncthreads();
    }

#pragma unroll
    for (int i = 0; i < 8; i++) {
        int w = m0 + rowoff(i, ty);
#pragma unroll
        for (int half = 0; half < 2; half++) {
            int f = n0 + half * 64 + tx * 4;
            float v0 = acc[i][half * 4 + 0], v1 = acc[i][half * 4 + 1];
            float v2 = acc[i][half * 4 + 2], v3 = acc[i][half * 4 + 3];
            if (do_rope) {
                int j0 = (f & 127) >> 1;
                float c0 = g_cos[w * 64 + j0], s0 = g_sin[w * 64 + j0];
                float c1 = g_cos[w * 64 + j0 + 1], s1 = g_sin[w * 64 + j0 + 1];
                float e0 = v0 * c0 - v1 * s0, o0 = v1 * c0 + v0 * s0;
                float e1 = v2 * c1 - v3 * s1, o1 = v3 * c1 + v2 * s1;
                v0 = e0; v1 = o0; v2 = e1; v3 = o1;
            }
            *(float4*)&Out[(size_t)w * 1024 + f] = make_float4(v0, v1, v2, v3);
        }
    }
}

// ---------------- S = q k^T / 32 + prev_qk + mask  (written to qk output) ----------------
__global__ __launch_bounds__(256) void gemm_qk_kernel(const float* __restrict__ prev_qk,
                                                      const float* __restrict__ mask,
                                                      float* __restrict__ qk_out) {
    const int m0 = blockIdx.x * 128;
    const int n0 = blockIdx.y * 128;
    const int bh = blockIdx.z;
    const int b4 = bh >> 3, head = bh & 7;
    const float* Qb = g_t[0][b4] + head * 128;
    const float* Kb = g_t[1][b4] + head * 128;

    __shared__ float As[8 * 132];
    __shared__ float Bs[8 * 132];
    const int tid = threadIdx.x;
    const int tx = tid & 15, ty = tid >> 4;
    const int ra = tid >> 1, ka = (tid & 1) * 4;

    float acc[8][8];
#pragma unroll
    for (int i = 0; i < 8; i++)
#pragma unroll
        for (int j = 0; j < 8; j++) acc[i][j] = 0.f;

    float4 pa = *(const float4*)&Qb[(size_t)(m0 + ra) * 1024 + ka];
    float4 pb = *(const float4*)&Kb[(size_t)(n0 + ra) * 1024 + ka];

    for (int k0 = 0; k0 < 128; k0 += 8) {
        As[(ka + 0) * 132 + ra] = pa.x;
        As[(ka + 1) * 132 + ra] = pa.y;
        As[(ka + 2) * 132 + ra] = pa.z;
        As[(ka + 3) * 132 + ra] = pa.w;
        Bs[(ka + 0) * 132 + ra] = pb.x;
        Bs[(ka + 1) * 132 + ra] = pb.y;
        Bs[(ka + 2) * 132 + ra] = pb.z;
        Bs[(ka + 3) * 132 + ra] = pb.w;
        __syncthreads();
        if (k0 + 8 < 128) {
            pa = *(const float4*)&Qb[(size_t)(m0 + ra) * 1024 + k0 + 8 + ka];
            pb = *(const float4*)&Kb[(size_t)(n0 + ra) * 1024 + k0 + 8 + ka];
        }
        gemm_step<132, 132>(As, Bs, tx, ty, acc);
        __syncthreads();
    }

    const float* prevb = prev_qk + ((size_t)bh << 20);
    float* outb = qk_out + ((size_t)bh << 20);
#pragma unroll
    for (int i = 0; i < 8; i++) {
        int mi = m0 + rowoff(i, ty);
#pragma unroll
        for (int half = 0; half < 2; half++) {
            int n = n0 + half * 64 + tx * 4;
            float4 pv = *(const float4*)&prevb[(size_t)mi * 1024 + n];
            float4 mk = *(const float4*)&mask[(size_t)mi * 1024 + n];
            float4 r;
            r.x = acc[i][half * 4 + 0] * 0.03125f + pv.x + mk.x;
            r.y = acc[i][half * 4 + 1] * 0.03125f + pv.y + mk.y;
            r.z = acc[i][half * 4 + 2] * 0.03125f + pv.z + mk.z;
            r.w = acc[i][half * 4 + 3] * 0.03125f + pv.w + mk.w;
            *(float4*)&outb[(size_t)mi * 1024 + n] = r;
        }
    }
}

// ---------------- row softmax stats over S ----------------
__global__ __launch_bounds__(256) void softmax_stats_kernel(const float* __restrict__ S) {
    int r = blockIdx.x;
    int tid = threadIdx.x;
    const float* row = S + ((size_t)r << 10);
    float4 v = *(const float4*)&row[tid * 4];
    float mx = fmaxf(fmaxf(v.x, v.y), fmaxf(v.z, v.w));
#pragma unroll
    for (int o = 16; o > 0; o >>= 1) mx = fmaxf(mx, __shfl_xor_sync(0xffffffffu, mx, o));
    __shared__ float sm[8];
    __shared__ float ss[8];
    if ((tid & 31) == 0) sm[tid >> 5] = mx;
    __syncthreads();
    float m8 = sm[0];
#pragma unroll
    for (int i = 1; i < 8; i++) m8 = fmaxf(m8, sm[i]);
    float se = __expf(v.x - m8) + __expf(v.y - m8) + __expf(v.z - m8) + __expf(v.w - m8);
#pragma unroll
    for (int o = 16; o > 0; o >>= 1) se += __shfl_xor_sync(0xffffffffu, se, o);
    if ((tid & 31) == 0) ss[tid >> 5] = se;
    __syncthreads();
    if (tid == 0) {
        float s = 0.f;
#pragma unroll
        for (int i = 0; i < 8; i++) s += ss[i];
        g_rmax[r] = m8;
        g_rinv[r] = 1.0f / s;
    }
}

// ---------------- A = softmax(S) @ V  (exp fused into A-tile load) ----------------
__global__ __launch_bounds__(256) void gemm_pv_kernel(const float* __restrict__ S) {
    const int m0 = blockIdx.x * 128;
    const int bh = blockIdx.y;
    const int b4 = bh >> 3, head = bh & 7;
    const float* Sb = S + ((size_t)bh << 20);
    const float* Vb = g_t[2][b4] + head * 128;
    float* Ab = g_a[b4];

    __shared__ float As[8 * 132];
    __shared__ float Bs[8 * 128];
    const int tid = threadIdx.x;
    const int tx = tid & 15, ty = tid >> 4;
    const int ra = tid >> 1, ka = (tid & 1) * 4;   // A transpose load (with exp)
    const int kb = tid >> 5, nbv = (tid & 31) * 4; // B direct load

    const float mx = g_rmax[bh * 1024 + m0 + ra];
    const float rv = g_rinv[bh * 1024 + m0 + ra];

    float acc[8][8];
#pragma unroll
    for (int i = 0; i < 8; i++)
#pragma unroll
        for (int j = 0; j < 8; j++) acc[i][j] = 0.f;

    float4 pa = *(const float4*)&Sb[(size_t)(m0 + ra) * 1024 + ka];
    float4 pb = *(const float4*)&Vb[(size_t)kb * 1024 + nbv];

    for (int k0 = 0; k0 < 1024; k0 += 8) {
        As[(ka + 0) * 132 + ra] = __expf(pa.x - mx) * rv;
        As[(ka + 1) * 132 + ra] = __expf(pa.y - mx) * rv;
        As[(ka + 2) * 132 + ra] = __expf(pa.z - mx) * rv;
        As[(ka + 3) * 132 + ra] = __expf(pa.w - mx) * rv;
        *(float4*)&Bs[kb * 128 + nbv] = pb;
        __syncthreads();
        if (k0 + 8 < 1024) {
            pa = *(const float4*)&Sb[(size_t)(m0 + ra) * 1024 + k0 + 8 + ka];
            pb = *(const float4*)&Vb[(size_t)(k0 + 8 + kb) * 1024 + nbv];
        }
        gemm_step<132, 128>(As, Bs, tx, ty, acc);
        __syncthreads();
    }

#pragma unroll
    for (int i = 0; i < 8; i++) {
        int mi = m0 + rowoff(i, ty);
#pragma unroll
        for (int half = 0; half < 2; half++) {
            int n = half * 64 + tx * 4;
            float4 r = make_float4(acc[i][half * 4 + 0], acc[i][half * 4 + 1],
                                   acc[i][half * 4 + 2], acc[i][half * 4 + 3]);
            *(float4*)&Ab[(size_t)mi * 1024 + head * 128 + n] = r;
        }
    }
}

// ---------------- 4x4 depthwise channel mix ----------------
__global__ __launch_bounds__(256) void dw_kernel(const float* __restrict__ dw) {
    int idx = blockIdx.x * 256 + threadIdx.x;  // 524288 total float4 slots
    int b = idx >> 18;
    size_t off = ((size_t)(idx & 262143)) << 2;
    float4 a[4];
#pragma unroll
    for (int c = 0; c < 4; c++) a[c] = *(const float4*)&g_a[b * 4 + c][off];
#pragma unroll
    for (int o = 0; o < 4; o++) {
        float w0 = dw[o * 4 + 0], w1 = dw[o * 4 + 1], w2 = dw[o * 4 + 2], w3 = dw[o * 4 + 3];
        float4 r;
        r.x = w0 * a[0].x + w1 * a[1].x + w2 * a[2].x + w3 * a[3].x;
        r.y = w0 * a[0].y + w1 * a[1].y + w2 * a[2].y + w3 * a[3].y;
        r.z = w0 * a[0].z + w1 * a[1].z + w2 * a[2].z + w3 * a[3].z;
        r.w = w0 * a[0].w + w1 * a[1].w + w2 * a[2].w + w3 * a[3].w;
        *(float4*)&g_ao[b * 4 + o][off] = r;
    }
}

// ---------------- wo_pw: Out[f,w] = sum_h Wt[f,h] * AoT[w,h] ----------------
__global__ __launch_bounds__(256) void gemm_wo_kernel(const float* __restrict__ Wopw) {
    const int m0 = blockIdx.x * 128;  // f
    const int n0 = blockIdx.y * 128;  // w
    const int b4 = blockIdx.z;
    const int am = b4 & 3;
    const float* Wt = Wopw + ((size_t)am << 20);
    const float* Ao = g_ao[b4];
    float* Out = g_a2[b4];

    __shared__ float As[8 * 132];
    __shared__ float Bs[8 * 132];
    const int tid = threadIdx.x;
    const int tx = tid & 15, ty = tid >> 4;
    const int ra = tid >> 1, ka = (tid & 1) * 4;

    float acc[8][8];
#pragma unroll
    for (int i = 0; i < 8; i++)
#pragma unroll
        for (int j = 0; j < 8; j++) acc[i][j] = 0.f;

    float4 pa = *(const float4*)&Wt[(size_t)(m0 + ra) * 1024 + ka];
    float4 pb = *(const float4*)&Ao[(size_t)(n0 + ra) * 1024 + ka];

    for (int k0 = 0; k0 < 1024; k0 += 8) {
        As[(ka + 0) * 132 + ra] = pa.x;
        As[(ka + 1) * 132 + ra] = pa.y;
        As[(ka + 2) * 132 + ra] = pa.z;
        As[(ka + 3) * 132 + ra] = pa.w;
        Bs[(ka + 0) * 132 + ra] = pb.x;
        Bs[(ka + 1) * 132 + ra] = pb.y;
        Bs[(ka + 2) * 132 + ra] = pb.z;
        Bs[(ka + 3) * 132 + ra] = pb.w;
        __syncthreads();
        if (k0 + 8 < 1024) {
            pa = *(const float4*)&Wt[(size_t)(m0 + ra) * 1024 + k0 + 8 + ka];
            pb = *(const float4*)&Ao[(size_t)(n0 + ra) * 1024 + k0 + 8 + ka];
        }
        gemm_step<132, 132>(As, Bs, tx, ty, acc);
        __syncthreads();
    }

#pragma unroll
    for (int i = 0; i < 8; i++) {
        int mi = m0 + rowoff(i, ty);
#pragma unroll
        for (int half = 0; half < 2; half++) {
            int n = n0 + half * 64 + tx * 4;
            float4 r = make_float4(acc[i][half * 4 + 0], acc[i][half * 4 + 1],
                                   acc[i][half * 4 + 2], acc[i][half * 4 + 3]);
            *(float4*)&Out[(size_t)mi * 1024 + n] = r;
        }
    }
}

// ---------------- final conv 3x3 over concat(x[16], a2[4]) -> 16 channels ----------------
__global__ __launch_bounds__(256) void conv_out_kernel(const float* __restrict__ x,
                                                       const float* __restrict__ wo,
                                                       const float* __restrict__ bo,
                                                       float* __restrict__ out) {
    __shared__ float sx[4][18][68];
    __shared__ float sw[16 * 20 * 9];  // 2880
    const int b = blockIdx.x;
    const int h0 = blockIdx.y * 16;
    const int w0 = blockIdx.z * 64;
    const int tx = threadIdx.x, ty = threadIdx.y;
    const int tid = ty * 16 + tx;

    for (int i = tid; i < 2880; i += 256) sw[i] = wo[i];

    float acc[16][4];
#pragma unroll
    for (int o = 0; o < 16; o++)
#pragma unroll
        for (int p = 0; p < 4; p++) acc[o][p] = 0.f;

    for (int cc = 0; cc < 20; cc += 4) {
        __syncthreads();
        for (int e = tid; e < 4 * 18 * 66; e += 256) {
            int ch = e / (18 * 66);
            int r = (e / 66) % 18;
            int cl = e % 66;
            int gh = h0 + r - 1, gw = w0 + cl - 1;
            int c = cc + ch;
            float v = 0.f;
            if ((unsigned)gh < 1024u && (unsigned)gw < 1024u) {
                const float* src = (c < 16) ? (x + (((size_t)(b * 16 + c)) << 20))
                                            : g_a2[b * 4 + (c - 16)];
                v = src[gh * 1024 + gw];
            }
            sx[ch][r][cl] = v;
        }
        __syncthreads();
#pragma unroll
        for (int ch = 0; ch < 4; ch++) {
#pragma unroll
            for (int dy = 0; dy < 3; dy++) {
                float xr[6];
#pragma unroll
                for (int i = 0; i < 6; i++) xr[i] = sx[ch][ty + dy][tx * 4 + i];
#pragma unroll
                for (int dx = 0; dx < 3; dx++) {
                    int widx = (cc + ch) * 9 + dy * 3 + dx;
#pragma unroll
                    for (int o = 0; o < 16; o++) {
                        float wv_ = sw[o * 180 + widx];
#pragma unroll
                        for (int p = 0; p < 4; p++) acc[o][p] += wv_ * xr[p + dx];
                    }
                }
            }
        }
    }

    int gh = h0 + ty, gw = w0 + tx * 4;
#pragma unroll
    for (int o = 0; o < 16; o++) {
        float bb = bo[o];
        float4 v = make_float4(acc[o][0] + bb, acc[o][1] + bb, acc[o][2] + bb, acc[o][3] + bb);
        *(float4*)&out[(((size_t)(b * 16 + o)) << 20) + gh * 1024 + gw] = v;
    }
}

// ---------------- launch ----------------
extern "C" void kernel_launch(void* const* d_in, const int* in_sizes, int n_in,
                              void* d_out, int out_size) {
    const float* x       = (const float*)d_in[0];
    const float* prev_qk = (const float*)d_in[1];
    const float* mask    = (const float*)d_in[2];
    const float* wq_conv = (const float*)d_in[3];
    const float* bq_conv = (const float*)d_in[4];
    const float* wq_pw   = (const float*)d_in[5];
    const float* wk_conv = (const float*)d_in[6];
    const float* bk_conv = (const float*)d_in[7];
    const float* wk_pw   = (const float*)d_in[8];
    const float* wv_conv = (const float*)d_in[9];
    const float* bv_conv = (const float*)d_in[10];
    const float* wv_pw   = (const float*)d_in[11];
    const float* wo_pw   = (const float*)d_in[12];
    const float* wo_dw   = (const float*)d_in[13];
    const float* wo_conv = (const float*)d_in[14];
    const float* bo_conv = (const float*)d_in[15];

    float* outp = (float*)d_out;                                   // (2,16,1024,1024)
    float* qk_out = outp + (size_t)NB * NC * NF * NW;              // (2,4,8,1024,1024)

    rope_init_kernel<<<64, 1024>>>();
    conv_qkv_kernel<<<dim3(NB, 64, 16), dim3(16, 16)>>>(x, wq_conv, bq_conv,
                                                        wk_conv, bk_conv, wv_conv, bv_conv);
    gemm_pw_kernel<<<dim3(8, 8, 8), 256>>>(wq_pw, 0, 1);
    gemm_pw_kernel<<<dim3(8, 8, 8), 256>>>(wk_pw, 1, 1);
    gemm_pw_kernel<<<dim3(8, 8, 8), 256>>>(wv_pw, 2, 0);
    gemm_qk_kernel<<<dim3(8, 8, 64), 256>>>(prev_qk, mask, qk_out);
    softmax_stats_kernel<<<65536, 256>>>(qk_out);
    gemm_pv_kernel<<<dim3(8, 64), 256>>>(qk_out);
    dw_kernel<<<2048, 256>>>(wo_dw);
    gemm_wo_kernel<<<dim3(8, 8, 8), 256>>>(wo_pw);
    conv_out_kernel<<<dim3(NB, 64, 16), dim3(16, 16)>>>(x, wo_conv, bo_conv, outp);
}

// round 2
// speedup vs baseline: 1.2175x; 1.2175x over previous
#include <cuda_runtime.h>
#include <math.h>

// Problem dims
#define NB 2
#define NC 16
#define NAM 4
#define NHEADS 8
#define NF 1024
#define NW 1024
#define NHD 128

#define SSTR 136  // smem row stride (words) -> conflict-free fragment loads

// ---------------- scratch (device globals; no runtime allocation) ----------------
__device__ float g_y[3][8][NF * NW];     // conv outputs for q,k,v   [tensor][b*4+am][h*1024+w]
__device__ float g_t[3][8][NW * NF];     // qT,kT,vT                 [tensor][b*4+am][w*1024+f]
__device__ float g_a[8][NW * NF];        // attention out            [b*4+am][w*1024+f]
__device__ float g_ao[8][NW * NF];       // after dw channel mix     [b*4+am][w*1024+h]
__device__ float g_a2[8][NF * NW];       // after wo_pw              [b*4+am][f*1024+w]
__device__ float g_rmax[NB * NAM * NHEADS * NW];
__device__ float g_rinv[NB * NAM * NHEADS * NW];
__device__ float g_cos[NW * (NHD / 2)];
__device__ float g_sin[NW * (NHD / 2)];

// ---------------- tf32 helpers ----------------
__device__ __forceinline__ unsigned f2tf(float x) {
    unsigned r;
    asm("cvt.rna.tf32.f32 %0, %1;" : "=r"(r) : "f"(x));
    return r;
}

__device__ __forceinline__ void mma_tf32(float* c, unsigned a0, unsigned a1, unsigned a2,
                                         unsigned a3, unsigned b0, unsigned b1) {
    asm volatile(
        "mma.sync.aligned.m16n8k8.row.col.f32.tf32.tf32.f32 "
        "{%0,%1,%2,%3}, {%4,%5,%6,%7}, {%8,%9}, {%0,%1,%2,%3};"
        : "+f"(c[0]), "+f"(c[1]), "+f"(c[2]), "+f"(c[3])
        : "r"(a0), "r"(a1), "r"(a2), "r"(a3), "r"(b0), "r"(b1));
}

// 128x128 C tile, BK=32. 8 warps as 4(M)x2(N); warp tile 32x64 = 2 x 8 mma frags.
__device__ __forceinline__ void tile_compute(const unsigned* As, const unsigned* Bs,
                                             float (&acc)[2][8][4], int lane, int warpM,
                                             int warpN) {
    const int gid = lane >> 2, tig = lane & 3;
#pragma unroll
    for (int kk = 0; kk < 4; kk++) {
        const int k = kk * 8;
        unsigned af[2][4];
#pragma unroll
        for (int mt = 0; mt < 2; mt++) {
            int rb = warpM * 32 + mt * 16 + gid;
            af[mt][0] = As[(k + tig) * SSTR + rb];
            af[mt][1] = As[(k + tig) * SSTR + rb + 8];
            af[mt][2] = As[(k + 4 + tig) * SSTR + rb];
            af[mt][3] = As[(k + 4 + tig) * SSTR + rb + 8];
        }
        unsigned bf[8][2];
#pragma unroll
        for (int nt = 0; nt < 8; nt++) {
            int cb = warpN * 64 + nt * 8 + gid;
            bf[nt][0] = Bs[(k + tig) * SSTR + cb];
            bf[nt][1] = Bs[(k + 4 + tig) * SSTR + cb];
        }
#pragma unroll
        for (int mt = 0; mt < 2; mt++)
#pragma unroll
            for (int nt = 0; nt < 8; nt++)
                mma_tf32(acc[mt][nt], af[mt][0], af[mt][1], af[mt][2], af[mt][3], bf[nt][0],
                         bf[nt][1]);
    }
}

// ---------------- RoPE table init ----------------
__global__ void rope_init_kernel() {
    int idx = blockIdx.x * blockDim.x + threadIdx.x;
    if (idx >= NW * 64) return;
    int w = idx >> 6, j = idx & 63;
    double inv = exp(-((double)(2 * j) / (double)NHD) * log(10000.0));
    double ang = (double)w * inv;
    g_cos[idx] = (float)cos(ang);
    g_sin[idx] = (float)sin(ang);
}

// ---------------- conv 3x3 (16 -> 4) producing q,k,v conv outputs in one pass ----------------
__global__ __launch_bounds__(256) void conv_qkv_kernel(
    const float* __restrict__ x,
    const float* __restrict__ wq, const float* __restrict__ bq,
    const float* __restrict__ wk, const float* __restrict__ bk,
    const float* __restrict__ wv, const float* __restrict__ bv) {
    __shared__ float sx[4][18][68];
    __shared__ float sw[3 * 4 * 16 * 9];
    const int b = blockIdx.x;
    const int h0 = blockIdx.y * 16;
    const int w0 = blockIdx.z * 64;
    const int tx = threadIdx.x, ty = threadIdx.y;
    const int tid = ty * 16 + tx;

    for (int i = tid; i < 576; i += 256) {
        sw[i] = wq[i];
        sw[576 + i] = wk[i];
        sw[1152 + i] = wv[i];
    }

    float acc[12][4];
#pragma unroll
    for (int o = 0; o < 12; o++)
#pragma unroll
        for (int p = 0; p < 4; p++) acc[o][p] = 0.f;

    for (int cc = 0; cc < 16; cc += 4) {
        __syncthreads();
        for (int e = tid; e < 4 * 18 * 66; e += 256) {
            int ch = e / (18 * 66);
            int r = (e / 66) % 18;
            int cl = e % 66;
            int gh = h0 + r - 1, gw = w0 + cl - 1;
            float v = 0.f;
            if ((unsigned)gh < 1024u && (unsigned)gw < 1024u)
                v = x[(((size_t)(b * 16 + cc + ch)) << 20) + gh * 1024 + gw];
            sx[ch][r][cl] = v;
        }
        __syncthreads();
#pragma unroll
        for (int ch = 0; ch < 4; ch++) {
#pragma unroll
            for (int dy = 0; dy < 3; dy++) {
                float xr[6];
#pragma unroll
                for (int i = 0; i < 6; i++) xr[i] = sx[ch][ty + dy][tx * 4 + i];
#pragma unroll
                for (int dx = 0; dx < 3; dx++) {
                    int widx = (cc + ch) * 9 + dy * 3 + dx;
#pragma unroll
                    for (int o = 0; o < 12; o++) {
                        float wv_ = sw[(o >> 2) * 576 + (o & 3) * 144 + widx];
#pragma unroll
                        for (int p = 0; p < 4; p++) acc[o][p] += wv_ * xr[p + dx];
                    }
                }
            }
        }
    }

    int gh = h0 + ty, gw = w0 + tx * 4;
#pragma unroll
    for (int t = 0; t < 3; t++) {
        const float* bias = (t == 0) ? bq : (t == 1) ? bk : bv;
#pragma unroll
        for (int m = 0; m < 4; m++) {
            float bb = bias[m];
            float4 v = make_float4(acc[t * 4 + m][0] + bb, acc[t * 4 + m][1] + bb,
                                   acc[t * 4 + m][2] + bb, acc[t * 4 + m][3] + bb);
            *(float4*)&g_y[t][b * 4 + m][gh * 1024 + gw] = v;
        }
    }
}

// ---------------- pw linear (tf32 mma): OutT[w,f] = sum_h Wt[f,h] * Y[h,w]; optional RoPE ----
__global__ __launch_bounds__(256) void gemm_pw_t(const float* __restrict__ Wpw, int t,
                                                 int do_rope) {
    const int m0 = blockIdx.x * 128;  // w
    const int n0 = blockIdx.y * 128;  // f
    const int b4 = blockIdx.z;
    const int am = b4 & 3;
    const float* Y = g_y[t][b4];
    const float* Wt = Wpw + ((size_t)am << 20);
    float* Out = g_t[t][b4];

    __shared__ unsigned As[32 * SSTR];
    __shared__ unsigned Bs[32 * SSTR];
    const int tid = threadIdx.x;
    const int lane = tid & 31, warp = tid >> 5, warpM = warp & 3, warpN = warp >> 2;
    const int gid = lane >> 2, tig = lane & 3;
    const int kA = tid >> 3, mA = (tid & 7) * 16;     // A: direct rows (k-major in gmem)
    const int nB = tid & 127, kB = (tid >> 7) * 16;   // B: transpose (n-major in gmem)

    float acc[2][8][4] = {};
    float4 pa[4], pb[4];
#pragma unroll
    for (int i = 0; i < 4; i++) {
        pa[i] = *(const float4*)&Y[(size_t)kA * 1024 + m0 + mA + i * 4];
        pb[i] = *(const float4*)&Wt[(size_t)(n0 + nB) * 1024 + kB + i * 4];
    }

    for (int k0 = 0; k0 < 1024; k0 += 32) {
#pragma unroll
        for (int i = 0; i < 4; i++) {
            As[kA * SSTR + mA + i * 4 + 0] = f2tf(pa[i].x);
            As[kA * SSTR + mA + i * 4 + 1] = f2tf(pa[i].y);
            As[kA * SSTR + mA + i * 4 + 2] = f2tf(pa[i].z);
            As[kA * SSTR + mA + i * 4 + 3] = f2tf(pa[i].w);
            Bs[(kB + i * 4 + 0) * SSTR + nB] = f2tf(pb[i].x);
            Bs[(kB + i * 4 + 1) * SSTR + nB] = f2tf(pb[i].y);
            Bs[(kB + i * 4 + 2) * SSTR + nB] = f2tf(pb[i].z);
            Bs[(kB + i * 4 + 3) * SSTR + nB] = f2tf(pb[i].w);
        }
        __syncthreads();
        if (k0 + 32 < 1024) {
#pragma unroll
            for (int i = 0; i < 4; i++) {
                pa[i] = *(const float4*)&Y[(size_t)(k0 + 32 + kA) * 1024 + m0 + mA + i * 4];
                pb[i] = *(const float4*)&Wt[(size_t)(n0 + nB) * 1024 + k0 + 32 + kB + i * 4];
            }
        }
        tile_compute(As, Bs, acc, lane, warpM, warpN);
        __syncthreads();
    }

#pragma unroll
    for (int mt = 0; mt < 2; mt++)
#pragma unroll
        for (int half = 0; half < 2; half++) {
            int w = m0 + warpM * 32 + mt * 16 + gid + half * 8;
#pragma unroll
            for (int nt = 0; nt < 8; nt++) {
                int f = n0 + warpN * 64 + nt * 8 + 2 * tig;
                float v0 = acc[mt][nt][half * 2 + 0];
                float v1 = acc[mt][nt][half * 2 + 1];
                if (do_rope) {
                    int j0 = (f >> 1) & 63;
                    float c = g_cos[w * 64 + j0], s = g_sin[w * 64 + j0];
                    float e = v0 * c - v1 * s, o = v1 * c + v0 * s;
                    v0 = e;
                    v1 = o;
                }
                *(float2*)&Out[(size_t)w * 1024 + f] = make_float2(v0, v1);
            }
        }
}

// ---------------- S = q k^T / 32 + prev_qk + mask  (tf32 mma) ----------------
__global__ __launch_bounds__(256) void gemm_qk_t(const float* __restrict__ prev_qk,
                                                 const float* __restrict__ mask,
                                                 float* __restrict__ qk_out) {
    const int m0 = blockIdx.x * 128;
    const int n0 = blockIdx.y * 128;
    const int bh = blockIdx.z;
    const int b4 = bh >> 3, head = bh & 7;
    const float* Qb = g_t[0][b4] + head * 128;
    const float* Kb = g_t[1][b4] + head * 128;

    __shared__ unsigned As[32 * SSTR];
    __shared__ unsigned Bs[32 * SSTR];
    const int tid = threadIdx.x;
    const int lane = tid & 31, warp = tid >> 5, warpM = warp & 3, warpN = warp >> 2;
    const int gid = lane >> 2, tig = lane & 3;
    const int rA = tid & 127, kA = (tid >> 7) * 16;  // both operands m/n-major -> transpose

    float acc[2][8][4] = {};
    float4 pa[4], pb[4];
#pragma unroll
    for (int i = 0; i < 4; i++) {
        pa[i] = *(const float4*)&Qb[(size_t)(m0 + rA) * 1024 + kA + i * 4];
        pb[i] = *(const float4*)&Kb[(size_t)(n0 + rA) * 1024 + kA + i * 4];
    }

    for (int k0 = 0; k0 < 128; k0 += 32) {
#pragma unroll
        for (int i = 0; i < 4; i++) {
            As[(kA + i * 4 + 0) * SSTR + rA] = f2tf(pa[i].x);
            As[(kA + i * 4 + 1) * SSTR + rA] = f2tf(pa[i].y);
            As[(kA + i * 4 + 2) * SSTR + rA] = f2tf(pa[i].z);
            As[(kA + i * 4 + 3) * SSTR + rA] = f2tf(pa[i].w);
            Bs[(kA + i * 4 + 0) * SSTR + rA] = f2tf(pb[i].x);
            Bs[(kA + i * 4 + 1) * SSTR + rA] = f2tf(pb[i].y);
            Bs[(kA + i * 4 + 2) * SSTR + rA] = f2tf(pb[i].z);
            Bs[(kA + i * 4 + 3) * SSTR + rA] = f2tf(pb[i].w);
        }
        __syncthreads();
        if (k0 + 32 < 128) {
#pragma unroll
            for (int i = 0; i < 4; i++) {
                pa[i] = *(const float4*)&Qb[(size_t)(m0 + rA) * 1024 + k0 + 32 + kA + i * 4];
                pb[i] = *(const float4*)&Kb[(size_t)(n0 + rA) * 1024 + k0 + 32 + kA + i * 4];
            }
        }
        tile_compute(As, Bs, acc, lane, warpM, warpN);
        __syncthreads();
    }

    const float* prevb = prev_qk + ((size_t)bh << 20);
    float* outb = qk_out + ((size_t)bh << 20);
#pragma unroll
    for (int mt = 0; mt < 2; mt++)
#pragma unroll
        for (int half = 0; half < 2; half++) {
            int mi = m0 + warpM * 32 + mt * 16 + gid + half * 8;
#pragma unroll
            for (int nt = 0; nt < 8; nt++) {
                int n = n0 + warpN * 64 + nt * 8 + 2 * tig;
                float2 pv = *(const float2*)&prevb[(size_t)mi * 1024 + n];
                float2 mk = *(const float2*)&mask[(size_t)mi * 1024 + n];
                float2 r;
                r.x = acc[mt][nt][half * 2 + 0] * 0.03125f + pv.x + mk.x;
                r.y = acc[mt][nt][half * 2 + 1] * 0.03125f + pv.y + mk.y;
                *(float2*)&outb[(size_t)mi * 1024 + n] = r;
            }
        }
}

// ---------------- row softmax stats over S ----------------
__global__ __launch_bounds__(256) void softmax_stats_kernel(const float* __restrict__ S) {
    int r = blockIdx.x;
    int tid = threadIdx.x;
    const float* row = S + ((size_t)r << 10);
    float4 v = *(const float4*)&row[tid * 4];
    float mx = fmaxf(fmaxf(v.x, v.y), fmaxf(v.z, v.w));
#pragma unroll
    for (int o = 16; o > 0; o >>= 1) mx = fmaxf(mx, __shfl_xor_sync(0xffffffffu, mx, o));
    __shared__ float sm[8];
    __shared__ float ss[8];
    if ((tid & 31) == 0) sm[tid >> 5] = mx;
    __syncthreads();
    float m8 = sm[0];
#pragma unroll
    for (int i = 1; i < 8; i++) m8 = fmaxf(m8, sm[i]);
    float se = __expf(v.x - m8) + __expf(v.y - m8) + __expf(v.z - m8) + __expf(v.w - m8);
#pragma unroll
    for (int o = 16; o > 0; o >>= 1) se += __shfl_xor_sync(0xffffffffu, se, o);
    if ((tid & 31) == 0) ss[tid >> 5] = se;
    __syncthreads();
    if (tid == 0) {
        float s = 0.f;
#pragma unroll
        for (int i = 0; i < 8; i++) s += ss[i];
        g_rmax[r] = m8;
        g_rinv[r] = 1.0f / s;
    }
}

// ---------------- A = softmax(S) @ V  (tf32 mma; exp fused into A-tile load) ----------------
__global__ __launch_bounds__(256) void gemm_pv_t(const float* __restrict__ S) {
    const int m0 = blockIdx.x * 128;
    const int bh = blockIdx.y;
    const int b4 = bh >> 3, head = bh & 7;
    const float* Sb = S + ((size_t)bh << 20);
    const float* Vb = g_t[2][b4] + head * 128;
    float* Ab = g_a[b4];

    __shared__ unsigned As[32 * SSTR];
    __shared__ unsigned Bs[32 * SSTR];
    const int tid = threadIdx.x;
    const int lane = tid & 31, warp = tid >> 5, warpM = warp & 3, warpN = warp >> 2;
    const int gid = lane >> 2, tig = lane & 3;
    const int rA = tid & 127, kA = (tid >> 7) * 16;  // A: transpose w/ exp
    const int kB = tid >> 3, nB4 = (tid & 7) * 16;   // B: direct rows

    const float mx = g_rmax[bh * 1024 + m0 + rA];
    const float rv = g_rinv[bh * 1024 + m0 + rA];

    float acc[2][8][4] = {};
    float4 pa[4], pb[4];
#pragma unroll
    for (int i = 0; i < 4; i++) {
        pa[i] = *(const float4*)&Sb[(size_t)(m0 + rA) * 1024 + kA + i * 4];
        pb[i] = *(const float4*)&Vb[(size_t)kB * 1024 + nB4 + i * 4];
    }

    for (int k0 = 0; k0 < 1024; k0 += 32) {
#pragma unroll
        for (int i = 0; i < 4; i++) {
            As[(kA + i * 4 + 0) * SSTR + rA] = f2tf(__expf(pa[i].x - mx) * rv);
            As[(kA + i * 4 + 1) * SSTR + rA] = f2tf(__expf(pa[i].y - mx) * rv);
            As[(kA + i * 4 + 2) * SSTR + rA] = f2tf(__expf(pa[i].z - mx) * rv);
            As[(kA + i * 4 + 3) * SSTR + rA] = f2tf(__expf(pa[i].w - mx) * rv);
            Bs[kB * SSTR + nB4 + i * 4 + 0] = f2tf(pb[i].x);
            Bs[kB * SSTR + nB4 + i * 4 + 1] = f2tf(pb[i].y);
            Bs[kB * SSTR + nB4 + i * 4 + 2] = f2tf(pb[i].z);
            Bs[kB * SSTR + nB4 + i * 4 + 3] = f2tf(pb[i].w);
        }
        __syncthreads();
        if (k0 + 32 < 1024) {
#pragma unroll
            for (int i = 0; i < 4; i++) {
                pa[i] = *(const float4*)&Sb[(size_t)(m0 + rA) * 1024 + k0 + 32 + kA + i * 4];
                pb[i] = *(const float4*)&Vb[(size_t)(k0 + 32 + kB) * 1024 + nB4 + i * 4];
            }
        }
        tile_compute(As, Bs, acc, lane, warpM, warpN);
        __syncthreads();
    }

#pragma unroll
    for (int mt = 0; mt < 2; mt++)
#pragma unroll
        for (int half = 0; half < 2; half++) {
            int mi = m0 + warpM * 32 + mt * 16 + gid + half * 8;
#pragma unroll
            for (int nt = 0; nt < 8; nt++) {
                int n = warpN * 64 + nt * 8 + 2 * tig;
                float2 r = make_float2(acc[mt][nt][half * 2 + 0], acc[mt][nt][half * 2 + 1]);
                *(float2*)&Ab[(size_t)mi * 1024 + head * 128 + n] = r;
            }
        }
}

// ---------------- 4x4 depthwise channel mix ----------------
__global__ __launch_bounds__(256) void dw_kernel(const float* __restrict__ dw) {
    int idx = blockIdx.x * 256 + threadIdx.x;
    int b = idx >> 18;
    size_t off = ((size_t)(idx & 262143)) << 2;
    float4 a[4];
#pragma unroll
    for (int c = 0; c < 4; c++) a[c] = *(const float4*)&g_a[b * 4 + c][off];
#pragma unroll
    for (int o = 0; o < 4; o++) {
        float w0 = dw[o * 4 + 0], w1 = dw[o * 4 + 1], w2 = dw[o * 4 + 2], w3 = dw[o * 4 + 3];
        float4 r;
        r.x = w0 * a[0].x + w1 * a[1].x + w2 * a[2].x + w3 * a[3].x;
        r.y = w0 * a[0].y + w1 * a[1].y + w2 * a[2].y + w3 * a[3].y;
        r.z = w0 * a[0].z + w1 * a[1].z + w2 * a[2].z + w3 * a[3].z;
        r.w = w0 * a[0].w + w1 * a[1].w + w2 * a[2].w + w3 * a[3].w;
        *(float4*)&g_ao[b * 4 + o][off] = r;
    }
}

// ---------------- wo_pw (tf32 mma): Out[f,w] = sum_h Wt[f,h] * AoT[w,h] ----------------
__global__ __launch_bounds__(256) void gemm_wo_t(const float* __restrict__ Wopw) {
    const int m0 = blockIdx.x * 128;  // f
    const int n0 = blockIdx.y * 128;  // w
    const int b4 = blockIdx.z;
    const int am = b4 & 3;
    const float* Wt = Wopw + ((size_t)am << 20);
    const float* Ao = g_ao[b4];
    float* Out = g_a2[b4];

    __shared__ unsigned As[32 * SSTR];
    __shared__ unsigned Bs[32 * SSTR];
    const int tid = threadIdx.x;
    const int lane = tid & 31, warp = tid >> 5, warpM = warp & 3, warpN = warp >> 2;
    const int gid = lane >> 2, tig = lane & 3;
    const int rA = tid & 127, kA = (tid >> 7) * 16;

    float acc[2][8][4] = {};
    float4 pa[4], pb[4];
#pragma unroll
    for (int i = 0; i < 4; i++) {
        pa[i] = *(const float4*)&Wt[(size_t)(m0 + rA) * 1024 + kA + i * 4];
        pb[i] = *(const float4*)&Ao[(size_t)(n0 + rA) * 1024 + kA + i * 4];
    }

    for (int k0 = 0; k0 < 1024; k0 += 32) {
#pragma unroll
        for (int i = 0; i < 4; i++) {
            As[(kA + i * 4 + 0) * SSTR + rA] = f2tf(pa[i].x);
            As[(kA + i * 4 + 1) * SSTR + rA] = f2tf(pa[i].y);
            As[(kA + i * 4 + 2) * SSTR + rA] = f2tf(pa[i].z);
            As[(kA + i * 4 + 3) * SSTR + rA] = f2tf(pa[i].w);
            Bs[(kA + i * 4 + 0) * SSTR + rA] = f2tf(pb[i].x);
            Bs[(kA + i * 4 + 1) * SSTR + rA] = f2tf(pb[i].y);
            Bs[(kA + i * 4 + 2) * SSTR + rA] = f2tf(pb[i].z);
            Bs[(kA + i * 4 + 3) * SSTR + rA] = f2tf(pb[i].w);
        }
        __syncthreads();
        if (k0 + 32 < 1024) {
#pragma unroll
            for (int i = 0; i < 4; i++) {
                pa[i] = *(const float4*)&Wt[(size_t)(m0 + rA) * 1024 + k0 + 32 + kA + i * 4];
                pb[i] = *(const float4*)&Ao[(size_t)(n0 + rA) * 1024 + k0 + 32 + kA + i * 4];
            }
        }
        tile_compute(As, Bs, acc, lane, warpM, warpN);
        __syncthreads();
    }

#pragma unroll
    for (int mt = 0; mt < 2; mt++)
#pragma unroll
        for (int half = 0; half < 2; half++) {
            int mi = m0 + warpM * 32 + mt * 16 + gid + half * 8;
#pragma unroll
            for (int nt = 0; nt < 8; nt++) {
                int n = n0 + warpN * 64 + nt * 8 + 2 * tig;
                float2 r = make_float2(acc[mt][nt][half * 2 + 0], acc[mt][nt][half * 2 + 1]);
                *(float2*)&Out[(size_t)mi * 1024 + n] = r;
            }
        }
}

// ---------------- final conv 3x3 over concat(x[16], a2[4]) -> 16 channels ----------------
__global__ __launch_bounds__(256) void conv_out_kernel(const float* __restrict__ x,
                                                       const float* __restrict__ wo,
                                                       const float* __restrict__ bo,
                                                       float* __restrict__ out) {
    __shared__ float sx[4][18][68];
    __shared__ float sw[16 * 20 * 9];
    const int b = blockIdx.x;
    const int h0 = blockIdx.y * 16;
    const int w0 = blockIdx.z * 64;
    const int tx = threadIdx.x, ty = threadIdx.y;
    const int tid = ty * 16 + tx;

    for (int i = tid; i < 2880; i += 256) sw[i] = wo[i];

    float acc[16][4];
#pragma unroll
    for (int o = 0; o < 16; o++)
#pragma unroll
        for (int p = 0; p < 4; p++) acc[o][p] = 0.f;

    for (int cc = 0; cc < 20; cc += 4) {
        __syncthreads();
        for (int e = tid; e < 4 * 18 * 66; e += 256) {
            int ch = e / (18 * 66);
            int r = (e / 66) % 18;
            int cl = e % 66;
            int gh = h0 + r - 1, gw = w0 + cl - 1;
            int c = cc + ch;
            float v = 0.f;
            if ((unsigned)gh < 1024u && (unsigned)gw < 1024u) {
                const float* src = (c < 16) ? (x + (((size_t)(b * 16 + c)) << 20))
                                            : g_a2[b * 4 + (c - 16)];
                v = src[gh * 1024 + gw];
            }
            sx[ch][r][cl] = v;
        }
        __syncthreads();
#pragma unroll
        for (int ch = 0; ch < 4; ch++) {
#pragma unroll
            for (int dy = 0; dy < 3; dy++) {
                float xr[6];
#pragma unroll
                for (int i = 0; i < 6; i++) xr[i] = sx[ch][ty + dy][tx * 4 + i];
#pragma unroll
                for (int dx = 0; dx < 3; dx++) {
                    int widx = (cc + ch) * 9 + dy * 3 + dx;
#pragma unroll
                    for (int o = 0; o < 16; o++) {
                        float wv_ = sw[o * 180 + widx];
#pragma unroll
                        for (int p = 0; p < 4; p++) acc[o][p] += wv_ * xr[p + dx];
                    }
                }
            }
        }
    }

    int gh = h0 + ty, gw = w0 + tx * 4;
#pragma unroll
    for (int o = 0; o < 16; o++) {
        float bb = bo[o];
        float4 v = make_float4(acc[o][0] + bb, acc[o][1] + bb, acc[o][2] + bb, acc[o][3] + bb);
        *(float4*)&out[(((size_t)(b * 16 + o)) << 20) + gh * 1024 + gw] = v;
    }
}

// ---------------- launch ----------------
extern "C" void kernel_launch(void* const* d_in, const int* in_sizes, int n_in,
                              void* d_out, int out_size) {
    const float* x       = (const float*)d_in[0];
    const float* prev_qk = (const float*)d_in[1];
    const float* mask    = (const float*)d_in[2];
    const float* wq_conv = (const float*)d_in[3];
    const float* bq_conv = (const float*)d_in[4];
    const float* wq_pw   = (const float*)d_in[5];
    const float* wk_conv = (const float*)d_in[6];
    const float* bk_conv = (const float*)d_in[7];
    const float* wk_pw   = (const float*)d_in[8];
    const float* wv_conv = (const float*)d_in[9];
    const float* bv_conv = (const float*)d_in[10];
    const float* wv_pw   = (const float*)d_in[11];
    const float* wo_pw   = (const float*)d_in[12];
    const float* wo_dw   = (const float*)d_in[13];
    const float* wo_conv = (const float*)d_in[14];
    const float* bo_conv = (const float*)d_in[15];

    float* outp = (float*)d_out;                       // (2,16,1024,1024)
    float* qk_out = outp + (size_t)NB * NC * NF * NW;  // (2,4,8,1024,1024)

    rope_init_kernel<<<64, 1024>>>();
    conv_qkv_kernel<<<dim3(NB, 64, 16), dim3(16, 16)>>>(x, wq_conv, bq_conv,
                                                        wk_conv, bk_conv, wv_conv, bv_conv);
    gemm_pw_t<<<dim3(8, 8, 8), 256>>>(wq_pw, 0, 1);
    gemm_pw_t<<<dim3(8, 8, 8), 256>>>(wk_pw, 1, 1);
    gemm_pw_t<<<dim3(8, 8, 8), 256>>>(wv_pw, 2, 0);
    gemm_qk_t<<<dim3(8, 8, 64), 256>>>(prev_qk, mask, qk_out);
    softmax_stats_kernel<<<65536, 256>>>(qk_out);
    gemm_pv_t<<<dim3(8, 64), 256>>>(qk_out);
    dw_kernel<<<2048, 256>>>(wo_dw);
    gemm_wo_t<<<dim3(8, 8, 8), 256>>>(wo_pw);
    conv_out_kernel<<<dim3(NB, 64, 16), dim3(16, 16)>>>(x, wo_conv, bo_conv, outp);
}

// round 3
// speedup vs baseline: 1.5683x; 1.2881x over previous
#include <cuda_runtime.h>
#include <math.h>

// Problem dims
#define NB 2
#define NC 16
#define NAM 4
#define NHEADS 8
#define NF 1024
#define NW 1024
#define NHD 128

#define BKDIM 16
#define STR_K 136  // k-major smem stride (words): 136 % 32 == 8 -> conflict-free frags
#define STR_M 20   // m-major smem stride (words): 20 % 32 == 20 -> conflict-free frags

// ---------------- scratch (device globals; no runtime allocation) ----------------
__device__ float g_y[3][8][NF * NW];     // conv outputs for q,k,v   [tensor][b*4+am][h*1024+w]
__device__ float g_t[3][8][NW * NF];     // qT,kT,vT                 [tensor][b*4+am][w*1024+f]
__device__ float g_a[8][NW * NF];        // attention out            [b*4+am][w*1024+f]
__device__ float g_ao[8][NW * NF];       // after dw channel mix     [b*4+am][w*1024+h]
__device__ float g_a2[8][NF * NW];       // after wo_pw              [b*4+am][f*1024+w]
__device__ float g_rmax[NB * NAM * NHEADS * NW];
__device__ float g_rinv[NB * NAM * NHEADS * NW];
__device__ float g_cos[NW * (NHD / 2)];
__device__ float g_sin[NW * (NHD / 2)];

// ---------------- async-copy helpers ----------------
__device__ __forceinline__ unsigned sptr(const void* p) {
    return (unsigned)__cvta_generic_to_shared(p);
}
__device__ __forceinline__ void cpasync16(const void* dst_smem, const void* src_gmem) {
    asm volatile("cp.async.cg.shared.global [%0], [%1], 16;" ::"r"(sptr(dst_smem)),
                 "l"(src_gmem));
}
#define CP_COMMIT asm volatile("cp.async.commit_group;")
#define CP_WAIT0 asm volatile("cp.async.wait_group 0;")

// ---------------- mma ----------------
__device__ __forceinline__ void mma_tf32(float* c, unsigned a0, unsigned a1, unsigned a2,
                                         unsigned a3, unsigned b0, unsigned b1) {
    asm volatile(
        "mma.sync.aligned.m16n8k8.row.col.f32.tf32.tf32.f32 "
        "{%0,%1,%2,%3}, {%4,%5,%6,%7}, {%8,%9}, {%0,%1,%2,%3};"
        : "+f"(c[0]), "+f"(c[1]), "+f"(c[2]), "+f"(c[3])
        : "r"(a0), "r"(a1), "r"(a2), "r"(a3), "r"(b0), "r"(b1));
}

// 128x128 C tile. 8 warps as 4(M)x2(N); warp tile 32x64 = 2 x 8 mma frags.
// AKM/BKM: operand stored k-major ([k][mn], stride STR_K) vs m-major ([mn][k], stride STR_M).
template <bool AKM, bool BKM>
__device__ __forceinline__ void frag_compute(const float* As, const float* Bs,
                                             float (&acc)[2][8][4], int gid, int tig,
                                             int warpM, int warpN) {
#pragma unroll
    for (int kk = 0; kk < 2; kk++) {
        const int k = kk * 8;
        unsigned af[2][4];
#pragma unroll
        for (int mt = 0; mt < 2; mt++) {
            int rb = warpM * 32 + mt * 16 + gid;
            af[mt][0] = __float_as_uint(AKM ? As[(k + tig) * STR_K + rb]
                                            : As[rb * STR_M + k + tig]);
            af[mt][1] = __float_as_uint(AKM ? As[(k + tig) * STR_K + rb + 8]
                                            : As[(rb + 8) * STR_M + k + tig]);
            af[mt][2] = __float_as_uint(AKM ? As[(k + 4 + tig) * STR_K + rb]
                                            : As[rb * STR_M + k + 4 + tig]);
            af[mt][3] = __float_as_uint(AKM ? As[(k + 4 + tig) * STR_K + rb + 8]
                                            : As[(rb + 8) * STR_M + k + 4 + tig]);
        }
        unsigned bf[8][2];
#pragma unroll
        for (int nt = 0; nt < 8; nt++) {
            int cb = warpN * 64 + nt * 8 + gid;
            bf[nt][0] = __float_as_uint(BKM ? Bs[(k + tig) * STR_K + cb]
                                            : Bs[cb * STR_M + k + tig]);
            bf[nt][1] = __float_as_uint(BKM ? Bs[(k + 4 + tig) * STR_K + cb]
                                            : Bs[cb * STR_M + k + 4 + tig]);
        }
#pragma unroll
        for (int mt = 0; mt < 2; mt++)
#pragma unroll
            for (int nt = 0; nt < 8; nt++)
                mma_tf32(acc[mt][nt], af[mt][0], af[mt][1], af[mt][2], af[mt][3], bf[nt][0],
                         bf[nt][1]);
    }
}

// copy one 16(k) x 128(mn) k-major slab: src rows contiguous in mn
__device__ __forceinline__ void copy_kmaj(float* buf, const float* src, int tid) {
#pragma unroll
    for (int i = 0; i < 2; i++) {
        int idx = tid + i * 256;
        int row = idx >> 5, c = (idx & 31) * 4;
        cpasync16(&buf[row * STR_K + c], &src[(size_t)row * 1024 + c]);
    }
}
// copy one 128(mn) x 16(k) m-major slab: src rows contiguous in k
__device__ __forceinline__ void copy_mmaj(float* buf, const float* src, int tid) {
#pragma unroll
    for (int i = 0; i < 2; i++) {
        int idx = tid + i * 256;
        int row = idx >> 2, c = (idx & 3) * 4;
        cpasync16(&buf[row * STR_M + c], &src[(size_t)row * 1024 + c]);
    }
}

// ---------------- RoPE table init ----------------
__global__ void rope_init_kernel() {
    int idx = blockIdx.x * blockDim.x + threadIdx.x;
    if (idx >= NW * 64) return;
    int w = idx >> 6, j = idx & 63;
    double inv = exp(-((double)(2 * j) / (double)NHD) * log(10000.0));
    double ang = (double)w * inv;
    g_cos[idx] = (float)cos(ang);
    g_sin[idx] = (float)sin(ang);
}

// ---------------- conv 3x3 (16 -> 4) producing q,k,v conv outputs in one pass ----------------
__global__ __launch_bounds__(256) void conv_qkv_kernel(
    const float* __restrict__ x,
    const float* __restrict__ wq, const float* __restrict__ bq,
    const float* __restrict__ wk, const float* __restrict__ bk,
    const float* __restrict__ wv, const float* __restrict__ bv) {
    __shared__ float sx[4][18][68];
    __shared__ float sw[3 * 4 * 16 * 9];
    const int b = blockIdx.x;
    const int h0 = blockIdx.y * 16;
    const int w0 = blockIdx.z * 64;
    const int tx = threadIdx.x, ty = threadIdx.y;
    const int tid = ty * 16 + tx;

    for (int i = tid; i < 576; i += 256) {
        sw[i] = wq[i];
        sw[576 + i] = wk[i];
        sw[1152 + i] = wv[i];
    }

    float acc[12][4];
#pragma unroll
    for (int o = 0; o < 12; o++)
#pragma unroll
        for (int p = 0; p < 4; p++) acc[o][p] = 0.f;

    for (int cc = 0; cc < 16; cc += 4) {
        __syncthreads();
        for (int e = tid; e < 4 * 18 * 66; e += 256) {
            int ch = e / (18 * 66);
            int r = (e / 66) % 18;
            int cl = e % 66;
            int gh = h0 + r - 1, gw = w0 + cl - 1;
            float v = 0.f;
            if ((unsigned)gh < 1024u && (unsigned)gw < 1024u)
                v = x[(((size_t)(b * 16 + cc + ch)) << 20) + gh * 1024 + gw];
            sx[ch][r][cl] = v;
        }
        __syncthreads();
#pragma unroll
        for (int ch = 0; ch < 4; ch++) {
#pragma unroll
            for (int dy = 0; dy < 3; dy++) {
                float xr[6];
#pragma unroll
                for (int i = 0; i < 6; i++) xr[i] = sx[ch][ty + dy][tx * 4 + i];
#pragma unroll
                for (int dx = 0; dx < 3; dx++) {
                    int widx = (cc + ch) * 9 + dy * 3 + dx;
#pragma unroll
                    for (int o = 0; o < 12; o++) {
                        float wv_ = sw[(o >> 2) * 576 + (o & 3) * 144 + widx];
#pragma unroll
                        for (int p = 0; p < 4; p++) acc[o][p] += wv_ * xr[p + dx];
                    }
                }
            }
        }
    }

    int gh = h0 + ty, gw = w0 + tx * 4;
#pragma unroll
    for (int t = 0; t < 3; t++) {
        const float* bias = (t == 0) ? bq : (t == 1) ? bk : bv;
#pragma unroll
        for (int m = 0; m < 4; m++) {
            float bb = bias[m];
            float4 v = make_float4(acc[t * 4 + m][0] + bb, acc[t * 4 + m][1] + bb,
                                   acc[t * 4 + m][2] + bb, acc[t * 4 + m][3] + bb);
            *(float4*)&g_y[t][b * 4 + m][gh * 1024 + gw] = v;
        }
    }
}

// ---------------- pw linear: OutT[w,f] = sum_h Wt[f,h] * Y[h,w]; optional RoPE ----------------
__global__ __launch_bounds__(256, 2) void gemm_pw_t(const float* __restrict__ Wpw, int t,
                                                    int do_rope) {
    const int m0 = blockIdx.x * 128;  // w
    const int n0 = blockIdx.y * 128;  // f
    const int b4 = blockIdx.z;
    const int am = b4 & 3;
    const float* Y = g_y[t][b4];
    const float* Wt = Wpw + ((size_t)am << 20);
    float* Out = g_t[t][b4];

    __shared__ __align__(16) float As[2][BKDIM * STR_K];   // k-major
    __shared__ __align__(16) float Bs[2][128 * STR_M];     // n-major
    const int tid = threadIdx.x;
    const int lane = tid & 31, warp = tid >> 5, warpM = warp & 3, warpN = warp >> 2;
    const int gid = lane >> 2, tig = lane & 3;

    float acc[2][8][4] = {};

    copy_kmaj(As[0], Y + m0, tid);
    copy_mmaj(Bs[0], Wt + (size_t)n0 * 1024, tid);
    CP_COMMIT;

    for (int it = 0; it < 64; it++) {
        const int cur = it & 1;
        CP_WAIT0;
        __syncthreads();
        if (it + 1 < 64) {
            copy_kmaj(As[cur ^ 1], Y + (size_t)(it + 1) * 16 * 1024 + m0, tid);
            copy_mmaj(Bs[cur ^ 1], Wt + (size_t)n0 * 1024 + (it + 1) * 16, tid);
            CP_COMMIT;
        }
        frag_compute<true, false>(As[cur], Bs[cur], acc, gid, tig, warpM, warpN);
    }

#pragma unroll
    for (int mt = 0; mt < 2; mt++)
#pragma unroll
        for (int half = 0; half < 2; half++) {
            int w = m0 + warpM * 32 + mt * 16 + gid + half * 8;
#pragma unroll
            for (int nt = 0; nt < 8; nt++) {
                int f = n0 + warpN * 64 + nt * 8 + 2 * tig;
                float v0 = acc[mt][nt][half * 2 + 0];
                float v1 = acc[mt][nt][half * 2 + 1];
                if (do_rope) {
                    int j0 = (f >> 1) & 63;
                    float c = g_cos[w * 64 + j0], s = g_sin[w * 64 + j0];
                    float e = v0 * c - v1 * s, o = v1 * c + v0 * s;
                    v0 = e;
                    v1 = o;
                }
                *(float2*)&Out[(size_t)w * 1024 + f] = make_float2(v0, v1);
            }
        }
}

// ---------------- S = q k^T / 32 + prev_qk + mask ----------------
__global__ __launch_bounds__(256, 2) void gemm_qk_t(const float* __restrict__ prev_qk,
                                                    const float* __restrict__ mask,
                                                    float* __restrict__ qk_out) {
    const int m0 = blockIdx.x * 128;
    const int n0 = blockIdx.y * 128;
    const int bh = blockIdx.z;
    const int b4 = bh >> 3, head = bh & 7;
    const float* Qb = g_t[0][b4] + head * 128;
    const float* Kb = g_t[1][b4] + head * 128;

    __shared__ __align__(16) float As[2][128 * STR_M];
    __shared__ __align__(16) float Bs[2][128 * STR_M];
    const int tid = threadIdx.x;
    const int lane = tid & 31, warp = tid >> 5, warpM = warp & 3, warpN = warp >> 2;
    const int gid = lane >> 2, tig = lane & 3;

    float acc[2][8][4] = {};

    copy_mmaj(As[0], Qb + (size_t)m0 * 1024, tid);
    copy_mmaj(Bs[0], Kb + (size_t)n0 * 1024, tid);
    CP_COMMIT;

    for (int it = 0; it < 8; it++) {
        const int cur = it & 1;
        CP_WAIT0;
        __syncthreads();
        if (it + 1 < 8) {
            copy_mmaj(As[cur ^ 1], Qb + (size_t)m0 * 1024 + (it + 1) * 16, tid);
            copy_mmaj(Bs[cur ^ 1], Kb + (size_t)n0 * 1024 + (it + 1) * 16, tid);
            CP_COMMIT;
        }
        frag_compute<false, false>(As[cur], Bs[cur], acc, gid, tig, warpM, warpN);
    }

    const float* prevb = prev_qk + ((size_t)bh << 20);
    float* outb = qk_out + ((size_t)bh << 20);
#pragma unroll
    for (int mt = 0; mt < 2; mt++)
#pragma unroll
        for (int half = 0; half < 2; half++) {
            int mi = m0 + warpM * 32 + mt * 16 + gid + half * 8;
#pragma unroll
            for (int nt = 0; nt < 8; nt++) {
                int n = n0 + warpN * 64 + nt * 8 + 2 * tig;
                float2 pv = *(const float2*)&prevb[(size_t)mi * 1024 + n];
                float2 mk = *(const float2*)&mask[(size_t)mi * 1024 + n];
                float2 r;
                r.x = acc[mt][nt][half * 2 + 0] * 0.03125f + pv.x + mk.x;
                r.y = acc[mt][nt][half * 2 + 1] * 0.03125f + pv.y + mk.y;
                *(float2*)&outb[(size_t)mi * 1024 + n] = r;
            }
        }
}

// ---------------- row softmax stats over S ----------------
__global__ __launch_bounds__(256) void softmax_stats_kernel(const float* __restrict__ S) {
    int r = blockIdx.x;
    int tid = threadIdx.x;
    const float* row = S + ((size_t)r << 10);
    float4 v = *(const float4*)&row[tid * 4];
    float mx = fmaxf(fmaxf(v.x, v.y), fmaxf(v.z, v.w));
#pragma unroll
    for (int o = 16; o > 0; o >>= 1) mx = fmaxf(mx, __shfl_xor_sync(0xffffffffu, mx, o));
    __shared__ float sm[8];
    __shared__ float ss[8];
    if ((tid & 31) == 0) sm[tid >> 5] = mx;
    __syncthreads();
    float m8 = sm[0];
#pragma unroll
    for (int i = 1; i < 8; i++) m8 = fmaxf(m8, sm[i]);
    float se = __expf(v.x - m8) + __expf(v.y - m8) + __expf(v.z - m8) + __expf(v.w - m8);
#pragma unroll
    for (int o = 16; o > 0; o >>= 1) se += __shfl_xor_sync(0xffffffffu, se, o);
    if ((tid & 31) == 0) ss[tid >> 5] = se;
    __syncthreads();
    if (tid == 0) {
        float s = 0.f;
#pragma unroll
        for (int i = 0; i < 8; i++) s += ss[i];
        g_rmax[r] = m8;
        g_rinv[r] = 1.0f / s;
    }
}

// ---------------- A = softmax(S) @ V  (exp in register path; V via cp.async) ----------------
__global__ __launch_bounds__(256, 2) void gemm_pv_t(const float* __restrict__ S) {
    const int m0 = blockIdx.x * 128;
    const int bh = blockIdx.y;
    const int b4 = bh >> 3, head = bh & 7;
    const float* Sb = S + ((size_t)bh << 20);
    const float* Vb = g_t[2][b4] + head * 128;
    float* Ab = g_a[b4];

    __shared__ __align__(16) float As[2][128 * STR_M];   // m-major P tile
    __shared__ __align__(16) float Bs[2][BKDIM * STR_K]; // k-major V tile
    const int tid = threadIdx.x;
    const int lane = tid & 31, warp = tid >> 5, warpM = warp & 3, warpN = warp >> 2;
    const int gid = lane >> 2, tig = lane & 3;

    const int arow = tid >> 1;       // local m row this thread stages
    const int aq = (tid & 1) * 8;    // k offset within slab
    const float mx = g_rmax[bh * 1024 + m0 + arow];
    const float rv = g_rinv[bh * 1024 + m0 + arow];
    const float* Srow = Sb + (size_t)(m0 + arow) * 1024;

    float acc[2][8][4] = {};
    float4 pa0 = *(const float4*)&Srow[aq];
    float4 pa1 = *(const float4*)&Srow[aq + 4];

    copy_kmaj(Bs[0], Vb, tid);
    CP_COMMIT;

    for (int it = 0; it < 64; it++) {
        const int cur = it & 1;
        CP_WAIT0;
        __syncthreads();
        {
            float* dst = &As[cur][arow * STR_M + aq];
            dst[0] = __expf(pa0.x - mx) * rv;
            dst[1] = __expf(pa0.y - mx) * rv;
            dst[2] = __expf(pa0.z - mx) * rv;
            dst[3] = __expf(pa0.w - mx) * rv;
            dst[4] = __expf(pa1.x - mx) * rv;
            dst[5] = __expf(pa1.y - mx) * rv;
            dst[6] = __expf(pa1.z - mx) * rv;
            dst[7] = __expf(pa1.w - mx) * rv;
        }
        if (it + 1 < 64) {
            pa0 = *(const float4*)&Srow[(it + 1) * 16 + aq];
            pa1 = *(const float4*)&Srow[(it + 1) * 16 + aq + 4];
            copy_kmaj(Bs[cur ^ 1], Vb + (size_t)(it + 1) * 16 * 1024, tid);
            CP_COMMIT;
        }
        __syncthreads();
        frag_compute<false, true>(As[cur], Bs[cur], acc, gid, tig, warpM, warpN);
    }

#pragma unroll
    for (int mt = 0; mt < 2; mt++)
#pragma unroll
        for (int half = 0; half < 2; half++) {
            int mi = m0 + warpM * 32 + mt * 16 + gid + half * 8;
#pragma unroll
            for (int nt = 0; nt < 8; nt++) {
                int n = warpN * 64 + nt * 8 + 2 * tig;
                float2 r = make_float2(acc[mt][nt][half * 2 + 0], acc[mt][nt][half * 2 + 1]);
                *(float2*)&Ab[(size_t)mi * 1024 + head * 128 + n] = r;
            }
        }
}

// ---------------- 4x4 depthwise channel mix ----------------
__global__ __launch_bounds__(256) void dw_kernel(const float* __restrict__ dw) {
    int idx = blockIdx.x * 256 + threadIdx.x;
    int b = idx >> 18;
    size_t off = ((size_t)(idx & 262143)) << 2;
    float4 a[4];
#pragma unroll
    for (int c = 0; c < 4; c++) a[c] = *(const float4*)&g_a[b * 4 + c][off];
#pragma unroll
    for (int o = 0; o < 4; o++) {
        float w0 = dw[o * 4 + 0], w1 = dw[o * 4 + 1], w2 = dw[o * 4 + 2], w3 = dw[o * 4 + 3];
        float4 r;
        r.x = w0 * a[0].x + w1 * a[1].x + w2 * a[2].x + w3 * a[3].x;
        r.y = w0 * a[0].y + w1 * a[1].y + w2 * a[2].y + w3 * a[3].y;
        r.z = w0 * a[0].z + w1 * a[1].z + w2 * a[2].z + w3 * a[3].z;
        r.w = w0 * a[0].w + w1 * a[1].w + w2 * a[2].w + w3 * a[3].w;
        *(float4*)&g_ao[b * 4 + o][off] = r;
    }
}

// ---------------- wo_pw: Out[f,w] = sum_h Wt[f,h] * AoT[w,h] ----------------
__global__ __launch_bounds__(256, 2) void gemm_wo_t(const float* __restrict__ Wopw) {
    const int m0 = blockIdx.x * 128;  // f
    const int n0 = blockIdx.y * 128;  // w
    const int b4 = blockIdx.z;
    const int am = b4 & 3;
    const float* Wt = Wopw + ((size_t)am << 20);
    const float* Ao = g_ao[b4];
    float* Out = g_a2[b4];

    __shared__ __align__(16) float As[2][128 * STR_M];
    __shared__ __align__(16) float Bs[2][128 * STR_M];
    const int tid = threadIdx.x;
    const int lane = tid & 31, warp = tid >> 5, warpM = warp & 3, warpN = warp >> 2;
    const int gid = lane >> 2, tig = lane & 3;

    float acc[2][8][4] = {};

    copy_mmaj(As[0], Wt + (size_t)m0 * 1024, tid);
    copy_mmaj(Bs[0], Ao + (size_t)n0 * 1024, tid);
    CP_COMMIT;

    for (int it = 0; it < 64; it++) {
        const int cur = it & 1;
        CP_WAIT0;
        __syncthreads();
        if (it + 1 < 64) {
            copy_mmaj(As[cur ^ 1], Wt + (size_t)m0 * 1024 + (it + 1) * 16, tid);
            copy_mmaj(Bs[cur ^ 1], Ao + (size_t)n0 * 1024 + (it + 1) * 16, tid);
            CP_COMMIT;
        }
        frag_compute<false, false>(As[cur], Bs[cur], acc, gid, tig, warpM, warpN);
    }

#pragma unroll
    for (int mt = 0; mt < 2; mt++)
#pragma unroll
        for (int half = 0; half < 2; half++) {
            int mi = m0 + warpM * 32 + mt * 16 + gid + half * 8;
#pragma unroll
            for (int nt = 0; nt < 8; nt++) {
                int n = n0 + warpN * 64 + nt * 8 + 2 * tig;
                float2 r = make_float2(acc[mt][nt][half * 2 + 0], acc[mt][nt][half * 2 + 1]);
                *(float2*)&Out[(size_t)mi * 1024 + n] = r;
            }
        }
}

// ---------------- final conv 3x3 over concat(x[16], a2[4]) -> 16 channels ----------------
__global__ __launch_bounds__(256) void conv_out_kernel(const float* __restrict__ x,
                                                       const float* __restrict__ wo,
                                                       const float* __restrict__ bo,
                                                       float* __restrict__ out) {
    __shared__ float sx[4][18][68];
    __shared__ float sw[16 * 20 * 9];
    const int b = blockIdx.x;
    const int h0 = blockIdx.y * 16;
    const int w0 = blockIdx.z * 64;
    const int tx = threadIdx.x, ty = threadIdx.y;
    const int tid = ty * 16 + tx;

    for (int i = tid; i < 2880; i += 256) sw[i] = wo[i];

    float acc[16][4];
#pragma unroll
    for (int o = 0; o < 16; o++)
#pragma unroll
        for (int p = 0; p < 4; p++) acc[o][p] = 0.f;

    for (int cc = 0; cc < 20; cc += 4) {
        __syncthreads();
        for (int e = tid; e < 4 * 18 * 66; e += 256) {
            int ch = e / (18 * 66);
            int r = (e / 66) % 18;
            int cl = e % 66;
            int gh = h0 + r - 1, gw = w0 + cl - 1;
            int c = cc + ch;
            float v = 0.f;
            if ((unsigned)gh < 1024u && (unsigned)gw < 1024u) {
                const float* src = (c < 16) ? (x + (((size_t)(b * 16 + c)) << 20))
                                            : g_a2[b * 4 + (c - 16)];
                v = src[gh * 1024 + gw];
            }
            sx[ch][r][cl] = v;
        }
        __syncthreads();
#pragma unroll
        for (int ch = 0; ch < 4; ch++) {
#pragma unroll
            for (int dy = 0; dy < 3; dy++) {
                float xr[6];
#pragma unroll
                for (int i = 0; i < 6; i++) xr[i] = sx[ch][ty + dy][tx * 4 + i];
#pragma unroll
                for (int dx = 0; dx < 3; dx++) {
                    int widx = (cc + ch) * 9 + dy * 3 + dx;
#pragma unroll
                    for (int o = 0; o < 16; o++) {
                        float wv_ = sw[o * 180 + widx];
#pragma unroll
                        for (int p = 0; p < 4; p++) acc[o][p] += wv_ * xr[p + dx];
                    }
                }
            }
        }
    }

    int gh = h0 + ty, gw = w0 + tx * 4;
#pragma unroll
    for (int o = 0; o < 16; o++) {
        float bb = bo[o];
        float4 v = make_float4(acc[o][0] + bb, acc[o][1] + bb, acc[o][2] + bb, acc[o][3] + bb);
        *(float4*)&out[(((size_t)(b * 16 + o)) << 20) + gh * 1024 + gw] = v;
    }
}

// ---------------- launch ----------------
extern "C" void kernel_launch(void* const* d_in, const int* in_sizes, int n_in,
                              void* d_out, int out_size) {
    const float* x       = (const float*)d_in[0];
    const float* prev_qk = (const float*)d_in[1];
    const float* mask    = (const float*)d_in[2];
    const float* wq_conv = (const float*)d_in[3];
    const float* bq_conv = (const float*)d_in[4];
    const float* wq_pw   = (const float*)d_in[5];
    const float* wk_conv = (const float*)d_in[6];
    const float* bk_conv = (const float*)d_in[7];
    const float* wk_pw   = (const float*)d_in[8];
    const float* wv_conv = (const float*)d_in[9];
    const float* bv_conv = (const float*)d_in[10];
    const float* wv_pw   = (const float*)d_in[11];
    const float* wo_pw   = (const float*)d_in[12];
    const float* wo_dw   = (const float*)d_in[13];
    const float* wo_conv = (const float*)d_in[14];
    const float* bo_conv = (const float*)d_in[15];

    float* outp = (float*)d_out;                       // (2,16,1024,1024)
    float* qk_out = outp + (size_t)NB * NC * NF * NW;  // (2,4,8,1024,1024)

    rope_init_kernel<<<64, 1024>>>();
    conv_qkv_kernel<<<dim3(NB, 64, 16), dim3(16, 16)>>>(x, wq_conv, bq_conv,
                                                        wk_conv, bk_conv, wv_conv, bv_conv);
    gemm_pw_t<<<dim3(8, 8, 8), 256>>>(wq_pw, 0, 1);
    gemm_pw_t<<<dim3(8, 8, 8), 256>>>(wk_pw, 1, 1);
    gemm_pw_t<<<dim3(8, 8, 8), 256>>>(wv_pw, 2, 0);
    gemm_qk_t<<<dim3(8, 8, 64), 256>>>(prev_qk, mask, qk_out);
    softmax_stats_kernel<<<65536, 256>>>(qk_out);
    gemm_pv_t<<<dim3(8, 64), 256>>>(qk_out);
    dw_kernel<<<2048, 256>>>(wo_dw);
    gemm_wo_t<<<dim3(8, 8, 8), 256>>>(wo_pw);
    conv_out_kernel<<<dim3(NB, 64, 16), dim3(16, 16)>>>(x, wo_conv, bo_conv, outp);
}